// round 3
// baseline (speedup 1.0000x reference)
#include <cuda_runtime.h>
#include <cstdint>

#define NB 4
#define NT 2048
#define NE 768
#define NH 3
#define ND 256
#define NM (NB*NT)          // 8192 rows

#define ATT_SCALE 0.022097086912079608f   // 1/sqrt(2048)

// Scratch (device globals: cudaMalloc is forbidden)
__device__ float g_Q[NB*NH*NT*ND];   // [b][h][t][d]
__device__ float g_K[NB*NH*NT*ND];
__device__ float g_V[NB*NH*NT*ND];
__device__ float g_Z[NB*NT*NE];      // attention output, [b][t][h*D+d]

// ===========================================================================
// 3xTF32 tensor-core GEMM core (m16n8k8 mma.sync).
// Tile 128x128xK, BK=16, 256 threads = 8 warps in 2(m) x 4(n); each warp
// computes 64x32 = 4x4 mma tiles. Operands split x = hi + lo (tf32 each);
// acc += hi*hi + hi*lo + lo*hi  (fp32-grade accuracy, ~2^-21 per product).
// ===========================================================================

__device__ __forceinline__ uint32_t f2tf(float x) {
    uint32_t r; asm("cvt.rna.tf32.f32 %0, %1;" : "=r"(r) : "f"(x)); return r;
}

__device__ __forceinline__ void mma8(float* c,
                                     uint32_t a0, uint32_t a1, uint32_t a2, uint32_t a3,
                                     uint32_t b0, uint32_t b1) {
    asm volatile("mma.sync.aligned.m16n8k8.row.col.f32.tf32.tf32.f32 "
                 "{%0,%1,%2,%3}, {%4,%5,%6,%7}, {%8,%9}, {%0,%1,%2,%3};"
                 : "+f"(c[0]), "+f"(c[1]), "+f"(c[2]), "+f"(c[3])
                 : "r"(a0), "r"(a1), "r"(a2), "r"(a3), "r"(b0), "r"(b1));
}

struct SmemG {
    // A: [k8][row][16 floats]: per k-slot j (0..3, swizzled by row&3):
    //    {hi(k=j), lo(k=j), hi(k=j+4), lo(k=j+4)}
    float A[2*128*16];        // 16 KB
    float Bh[16][136];        // B hi, [k][n], pad 136 (8 mod 32 -> conflict-free)
    float Bl[16][136];        // B lo
};

// Store one BK=16 A tile (this thread's 8 floats: row ar, ks ak8*8 .. +7)
__device__ __forceinline__ void store_A_tile(SmemG& s, int ar, int ak8,
                                             const float4& pa0, const float4& pa1)
{
    float v[8] = {pa0.x, pa0.y, pa0.z, pa0.w, pa1.x, pa1.y, pa1.z, pa1.w};
    float* base = s.A + (ak8*128 + ar)*16;
    const int sw = ar & 3;
#pragma unroll
    for (int j = 0; j < 4; j++) {
        float hi0 = __uint_as_float(f2tf(v[j]));
        float lo0 = __uint_as_float(f2tf(v[j]   - hi0));
        float hi1 = __uint_as_float(f2tf(v[j+4]));
        float lo1 = __uint_as_float(f2tf(v[j+4] - hi1));
        float* p = base + (j ^ sw) * 4;
        p[0] = hi0; p[1] = lo0; p[2] = hi1; p[3] = lo1;
    }
}

// Store one BK=16 B tile (this thread's 8 floats: k row bk, ns bn .. bn+7)
__device__ __forceinline__ void store_B_tile(SmemG& s, int bk, int bn,
                                             const float4& pb0, const float4& pb1)
{
    float v[8] = {pb0.x, pb0.y, pb0.z, pb0.w, pb1.x, pb1.y, pb1.z, pb1.w};
#pragma unroll
    for (int j = 0; j < 8; j++) {
        float hi = __uint_as_float(f2tf(v[j]));
        s.Bh[bk][bn + j] = hi;
        s.Bl[bk][bn + j] = __uint_as_float(f2tf(v[j] - hi));
    }
}

// A: tile base (128 rows, stride NE). B: tile base (768 k-rows, stride ldb).
__device__ __forceinline__ void gemm_tf32_core(
    const float* __restrict__ Ag, const float* __restrict__ Bg, int ldb,
    SmemG& s, float acc[4][4][4])
{
    const int tid  = threadIdx.x;
    const int lane = tid & 31, wid = tid >> 5;
    const int wm = wid >> 2, wn = wid & 3;
    const int g = lane >> 2, t = lane & 3;
    const int ar = tid >> 1, ak8 = tid & 1;      // A loader: row, k8-half
    const int bk = tid >> 4, bn = (tid & 15) * 8; // B loader: k-row, n-seg

#pragma unroll
    for (int mt = 0; mt < 4; mt++)
#pragma unroll
        for (int nt = 0; nt < 4; nt++)
#pragma unroll
            for (int i = 0; i < 4; i++) acc[mt][nt][i] = 0.f;

    float4 pa0 = *(const float4*)(Ag + (size_t)ar*NE + ak8*8);
    float4 pa1 = *(const float4*)(Ag + (size_t)ar*NE + ak8*8 + 4);
    float4 pb0 = *(const float4*)(Bg + (size_t)bk*ldb + bn);
    float4 pb1 = *(const float4*)(Bg + (size_t)bk*ldb + bn + 4);

    const int sw = t ^ (g & 3);   // row&3 == g&3 for all fragment rows

    for (int k0 = 0; k0 < NE; k0 += 16) {
        store_A_tile(s, ar, ak8, pa0, pa1);
        store_B_tile(s, bk, bn, pb0, pb1);
        __syncthreads();
        if (k0 + 16 < NE) {
            pa0 = *(const float4*)(Ag + (size_t)ar*NE + (k0+16) + ak8*8);
            pa1 = *(const float4*)(Ag + (size_t)ar*NE + (k0+16) + ak8*8 + 4);
            pb0 = *(const float4*)(Bg + (size_t)(k0+16+bk)*ldb + bn);
            pb1 = *(const float4*)(Bg + (size_t)(k0+16+bk)*ldb + bn + 4);
        }
#pragma unroll
        for (int k8i = 0; k8i < 2; k8i++) {
            uint32_t ah[4][4], al[4][4];
#pragma unroll
            for (int mt = 0; mt < 4; mt++) {
                const float* p0 = s.A + (size_t)(k8i*128 + wm*64 + mt*16 + g)*16 + sw*4;
                float4 fa = *(const float4*)p0;        // row g   : a0,a2 hi/lo
                float4 fb = *(const float4*)(p0 + 128); // row g+8 : a1,a3 hi/lo
                ah[mt][0] = __float_as_uint(fa.x); al[mt][0] = __float_as_uint(fa.y);
                ah[mt][2] = __float_as_uint(fa.z); al[mt][2] = __float_as_uint(fa.w);
                ah[mt][1] = __float_as_uint(fb.x); al[mt][1] = __float_as_uint(fb.y);
                ah[mt][3] = __float_as_uint(fb.z); al[mt][3] = __float_as_uint(fb.w);
            }
            const int kr0 = k8i*8 + t, kr1 = kr0 + 4;
#pragma unroll
            for (int nt = 0; nt < 4; nt++) {
                const int n = wn*32 + nt*8 + g;
                uint32_t bh0 = __float_as_uint(s.Bh[kr0][n]);
                uint32_t bh1 = __float_as_uint(s.Bh[kr1][n]);
                uint32_t bl0 = __float_as_uint(s.Bl[kr0][n]);
                uint32_t bl1 = __float_as_uint(s.Bl[kr1][n]);
#pragma unroll
                for (int mt = 0; mt < 4; mt++) {
                    mma8(acc[mt][nt], ah[mt][0], ah[mt][1], ah[mt][2], ah[mt][3], bh0, bh1);
                    mma8(acc[mt][nt], ah[mt][0], ah[mt][1], ah[mt][2], ah[mt][3], bl0, bl1);
                    mma8(acc[mt][nt], al[mt][0], al[mt][1], al[mt][2], al[mt][3], bh0, bh1);
                }
            }
        }
        __syncthreads();
    }
}

// ---------------------------------------------------------------------------
// QKV projection via 3xTF32: X[M,E] @ W[h][E][D] -> g_{Q,K,V}  [b][h][t][d]
// blockIdx.x in 0..5: head h = x>>1, d-half = (x&1)*128.
// ---------------------------------------------------------------------------
__global__ __launch_bounds__(256)
void proj_mma_kernel(const float* __restrict__ Xk, const float* __restrict__ Xv,
                     const float* __restrict__ Xq,
                     const float* __restrict__ Wk, const float* __restrict__ Wq,
                     const float* __restrict__ Wv)
{
    __shared__ SmemG s;
    const float* X; const float* W; float* Out;
    if (blockIdx.z == 0)      { X = Xq; W = Wq; Out = g_Q; }
    else if (blockIdx.z == 1) { X = Xk; W = Wk; Out = g_K; }
    else                      { X = Xv; W = Wv; Out = g_V; }

    const int m0  = blockIdx.y * 128;
    const int h   = blockIdx.x >> 1;
    const int dB0 = (blockIdx.x & 1) * 128;

    float acc[4][4][4];
    gemm_tf32_core(X + (size_t)m0*NE, W + (size_t)h*NE*ND + dB0, ND, s, acc);

    const int lane = threadIdx.x & 31, wid = threadIdx.x >> 5;
    const int wm = wid >> 2, wn = wid & 3, g = lane >> 2, t = lane & 3;
#pragma unroll
    for (int mt = 0; mt < 4; mt++) {
        int r0 = m0 + wm*64 + mt*16 + g;
        int r1 = r0 + 8;
        int bb0 = r0 >> 11, tt0 = r0 & (NT-1);
        int bb1 = r1 >> 11, tt1 = r1 & (NT-1);
        float* o0 = Out + ((size_t)(bb0*NH + h)*NT + tt0)*ND + dB0;
        float* o1 = Out + ((size_t)(bb1*NH + h)*NT + tt1)*ND + dB0;
#pragma unroll
        for (int nt = 0; nt < 4; nt++) {
            int c = wn*32 + nt*8 + 2*t;
            *(float2*)(o0 + c) = make_float2(acc[mt][nt][0], acc[mt][nt][1]);
            *(float2*)(o1 + c) = make_float2(acc[mt][nt][2], acc[mt][nt][3]);
        }
    }
}

// ---------------------------------------------------------------------------
// Output projection via 3xTF32: g_Z[M,E] @ Wo[E,E] + bo -> out[M,E]
// ---------------------------------------------------------------------------
__global__ __launch_bounds__(256)
void out_mma_kernel(const float* __restrict__ Wo, const float* __restrict__ bo,
                    float* __restrict__ out)
{
    __shared__ SmemG s;
    const int m0 = blockIdx.y * 128;
    const int c0 = blockIdx.x * 128;

    float acc[4][4][4];
    gemm_tf32_core(g_Z + (size_t)m0*NE, Wo + c0, NE, s, acc);

    const int lane = threadIdx.x & 31, wid = threadIdx.x >> 5;
    const int wm = wid >> 2, wn = wid & 3, g = lane >> 2, t = lane & 3;
#pragma unroll
    for (int mt = 0; mt < 4; mt++) {
        int r0 = m0 + wm*64 + mt*16 + g;
        int r1 = r0 + 8;
        float* o0 = out + (size_t)r0*NE + c0;
        float* o1 = out + (size_t)r1*NE + c0;
#pragma unroll
        for (int nt = 0; nt < 4; nt++) {
            int c = wn*32 + nt*8 + 2*t;
            float b0 = bo[c0 + c], b1 = bo[c0 + c + 1];
            *(float2*)(o0 + c) = make_float2(acc[mt][nt][0] + b0, acc[mt][nt][1] + b1);
            *(float2*)(o1 + c) = make_float2(acc[mt][nt][2] + b0, acc[mt][nt][3] + b1);
        }
    }
}

// ---------------------------------------------------------------------------
// Flash attention, causal, per (b,h). BQ=BKV=64, D=256 resident in smem.
// (unchanged from R1: fp32 FFMA, swizzled transposed Q/K, reversed qt order)
// ---------------------------------------------------------------------------
__global__ __launch_bounds__(256)
void attn_kernel()
{
    extern __shared__ float sm[];
    float* Qt  = sm;                  // [256][64] swizzled
    float* Kt  = Qt + 256*64;         // [256][64] swizzled
    float* Vs  = Kt + 256*64;         // [64][260]
    float* Ps  = Vs + 64*260;         // [64][68]
    float* m_s = Ps + 64*68;          // [64]
    float* l_s = m_s + 64;            // [64]
    float* al_s= l_s + 64;            // [64]

    const int tid = threadIdx.x;
    const int bh  = blockIdx.y;
    const int b   = bh / NH, h = bh % NH;
    const int qt  = (gridDim.x - 1) - blockIdx.x;   // heavy tiles first
    const int q0  = qt * 64;

    const size_t base = (size_t)(b*NH + h) * NT * ND;

    {
        const float* Qg = g_Q + base + (size_t)q0 * ND;
#pragma unroll
        for (int it = 0; it < 16; it++) {
            int idx = tid + it*256;
            int r  = idx >> 6;
            int f4 = idx & 63;
            float4 v = *(const float4*)(Qg + r*ND + f4*4);
            int col = r ^ ((f4 & 15) << 2);
            float* p = Qt + (f4*4)*64 + col;
            p[0] = v.x; p[64] = v.y; p[128] = v.z; p[192] = v.w;
        }
    }
    if (tid < 64) { m_s[tid] = -1e30f; l_s[tid] = 0.f; }

    float acc[4][4][4];
#pragma unroll
    for (int i = 0; i < 4; i++)
#pragma unroll
        for (int jb = 0; jb < 4; jb++)
#pragma unroll
            for (int u = 0; u < 4; u++) acc[i][jb][u] = 0.f;

    const int tyA = tid >> 4, txA = tid & 15;
    const int rS  = tid >> 2, gS  = tid & 3;

    for (int kt = 0; kt <= qt; kt++) {
        const int k0 = kt * 64;
        __syncthreads();

        {
            const float* Kg = g_K + base + (size_t)k0 * ND;
            const float* Vg = g_V + base + (size_t)k0 * ND;
#pragma unroll
            for (int it = 0; it < 16; it++) {
                int idx = tid + it*256;
                int r  = idx >> 6;
                int f4 = idx & 63;
                float4 v = *(const float4*)(Kg + r*ND + f4*4);
                int col = r ^ ((f4 & 15) << 2);
                float* p = Kt + (f4*4)*64 + col;
                p[0] = v.x; p[64] = v.y; p[128] = v.z; p[192] = v.w;
                float4 w = *(const float4*)(Vg + r*ND + f4*4);
                *(float4*)(Vs + r*260 + f4*4) = w;
            }
        }
        __syncthreads();

        {
            float s[4][4];
#pragma unroll
            for (int i = 0; i < 4; i++)
#pragma unroll
                for (int j = 0; j < 4; j++) s[i][j] = 0.f;
#pragma unroll 8
            for (int dd = 0; dd < ND; dd++) {
                int swz = ((dd >> 2) & 15) << 2;
                float4 av = *(const float4*)(Qt + dd*64 + ((tyA*4) ^ swz));
                float4 bv = *(const float4*)(Kt + dd*64 + ((txA*4) ^ swz));
                float a0 = av.x, a1 = av.y, a2 = av.z, a3 = av.w;
                s[0][0] += a0*bv.x; s[0][1] += a0*bv.y; s[0][2] += a0*bv.z; s[0][3] += a0*bv.w;
                s[1][0] += a1*bv.x; s[1][1] += a1*bv.y; s[1][2] += a1*bv.z; s[1][3] += a1*bv.w;
                s[2][0] += a2*bv.x; s[2][1] += a2*bv.y; s[2][2] += a2*bv.z; s[2][3] += a2*bv.w;
                s[3][0] += a3*bv.x; s[3][1] += a3*bv.y; s[3][2] += a3*bv.z; s[3][3] += a3*bv.w;
            }
#pragma unroll
            for (int i = 0; i < 4; i++) {
                float4 v;
                v.x = s[i][0]; v.y = s[i][1]; v.z = s[i][2]; v.w = s[i][3];
                *(float4*)(Ps + (tyA*4+i)*68 + txA*4) = v;
            }
        }
        __syncthreads();

        {
            float* Sr = Ps + rS*68 + gS*16;
            const bool diag = (kt == qt);
            float v[16];
            float mloc = -1e30f;
#pragma unroll
            for (int c = 0; c < 16; c++) {
                float x = Sr[c] * ATT_SCALE;
                if (diag && (gS*16 + c) > rS) x = -1e30f;
                v[c] = x;
                mloc = fmaxf(mloc, x);
            }
            mloc = fmaxf(mloc, __shfl_xor_sync(0xffffffffu, mloc, 1));
            mloc = fmaxf(mloc, __shfl_xor_sync(0xffffffffu, mloc, 2));
            float mold = m_s[rS];
            float mnew = fmaxf(mold, mloc);
            float suml = 0.f;
#pragma unroll
            for (int c = 0; c < 16; c++) {
                float p = __expf(v[c] - mnew);
                Sr[c] = p;
                suml += p;
            }
            suml += __shfl_xor_sync(0xffffffffu, suml, 1);
            suml += __shfl_xor_sync(0xffffffffu, suml, 2);
            if (gS == 0) {
                float alpha = __expf(mold - mnew);
                l_s[rS]  = l_s[rS]*alpha + suml;
                m_s[rS]  = mnew;
                al_s[rS] = alpha;
            }
        }
        __syncthreads();

        {
            float alr[4];
#pragma unroll
            for (int i = 0; i < 4; i++) alr[i] = al_s[tyA*4+i];
#pragma unroll
            for (int i = 0; i < 4; i++)
#pragma unroll
                for (int jb = 0; jb < 4; jb++)
#pragma unroll
                    for (int u = 0; u < 4; u++) acc[i][jb][u] *= alr[i];
#pragma unroll 2
            for (int kk = 0; kk < 64; kk++) {
                float a0 = Ps[(tyA*4+0)*68 + kk];
                float a1 = Ps[(tyA*4+1)*68 + kk];
                float a2 = Ps[(tyA*4+2)*68 + kk];
                float a3 = Ps[(tyA*4+3)*68 + kk];
#pragma unroll
                for (int jb = 0; jb < 4; jb++) {
                    float4 bv = *(const float4*)(Vs + kk*260 + jb*64 + txA*4);
                    acc[0][jb][0] += a0*bv.x; acc[0][jb][1] += a0*bv.y;
                    acc[0][jb][2] += a0*bv.z; acc[0][jb][3] += a0*bv.w;
                    acc[1][jb][0] += a1*bv.x; acc[1][jb][1] += a1*bv.y;
                    acc[1][jb][2] += a1*bv.z; acc[1][jb][3] += a1*bv.w;
                    acc[2][jb][0] += a2*bv.x; acc[2][jb][1] += a2*bv.y;
                    acc[2][jb][2] += a2*bv.z; acc[2][jb][3] += a2*bv.w;
                    acc[3][jb][0] += a3*bv.x; acc[3][jb][1] += a3*bv.y;
                    acc[3][jb][2] += a3*bv.z; acc[3][jb][3] += a3*bv.w;
                }
            }
        }
    }

    {
        float linv[4];
#pragma unroll
        for (int i = 0; i < 4; i++) linv[i] = __fdividef(1.0f, l_s[tyA*4+i]);
        float* Zg = g_Z + ((size_t)b*NT + q0)*NE + h*ND;
#pragma unroll
        for (int i = 0; i < 4; i++) {
            float* row = Zg + (size_t)(tyA*4+i)*NE;
#pragma unroll
            for (int jb = 0; jb < 4; jb++) {
                float4 v;
                v.x = acc[i][jb][0]*linv[i];
                v.y = acc[i][jb][1]*linv[i];
                v.z = acc[i][jb][2]*linv[i];
                v.w = acc[i][jb][3]*linv[i];
                *(float4*)(row + jb*64 + txA*4) = v;
            }
        }
    }
}

// ---------------------------------------------------------------------------
extern "C" void kernel_launch(void* const* d_in, const int* in_sizes, int n_in,
                              void* d_out, int out_size)
{
    const float* Xk = (const float*)d_in[0];   // inputs_for_keys
    const float* Xv = (const float*)d_in[1];   // inputs_for_values
    const float* Xq = (const float*)d_in[2];   // inputs_for_queries
    const float* Wk = (const float*)d_in[3];
    const float* Wq = (const float*)d_in[4];
    const float* Wv = (const float*)d_in[5];
    const float* Wo = (const float*)d_in[6];
    const float* bo = (const float*)d_in[7];
    float* out = (float*)d_out;

    dim3 gproj(NE/128, NM/128, 3);
    proj_mma_kernel<<<gproj, 256>>>(Xk, Xv, Xq, Wk, Wq, Wv);

    const size_t smemAttn =
        (size_t)(256*64 + 256*64 + 64*260 + 64*68 + 3*64) * sizeof(float); // 215,808 B
    cudaFuncSetAttribute(attn_kernel,
                         cudaFuncAttributeMaxDynamicSharedMemorySize,
                         (int)smemAttn);
    dim3 gattn(NT/64, NB*NH);
    attn_kernel<<<gattn, 256, smemAttn>>>();

    dim3 gout(NE/128, NM/128);
    out_mma_kernel<<<gout, 256>>>(Wo, bo, out);
}

// round 16
// speedup vs baseline: 2.7613x; 2.7613x over previous
#include <cuda_runtime.h>
#include <cstdint>

#define NB 4
#define NT 2048
#define NE 768
#define NH 3
#define ND 256
#define NM (NB*NT)          // 8192 rows

#define ATT_SCALE 0.022097086912079608f   // 1/sqrt(2048)

// Scratch (device globals: cudaMalloc is forbidden)
__device__ float g_Q[NB*NH*NT*ND];   // [b][h][t][d]
__device__ float g_K[NB*NH*NT*ND];
__device__ float g_V[NB*NH*NT*ND];
__device__ float g_Z[NB*NT*NE];      // attention output, [b][t][h*D+d]

// ===========================================================================
// Helpers: bf16 split / mma / ldmatrix
// ===========================================================================

// Split two fp32 into packed bf16x2 hi and lo planes.
// h2 = {bf16(y)<<16 | bf16(x)}; l2 = packed residuals. lo*lo term ~2^-18: dropped.
__device__ __forceinline__ void split2(float x, float y, uint32_t& h2, uint32_t& l2) {
    asm("cvt.rn.bf16x2.f32 %0, %1, %2;" : "=r"(h2) : "f"(y), "f"(x));
    float xh = __uint_as_float(h2 << 16);
    float yh = __uint_as_float(h2 & 0xffff0000u);
    asm("cvt.rn.bf16x2.f32 %0, %1, %2;" : "=r"(l2) : "f"(y - yh), "f"(x - xh));
}

__device__ __forceinline__ void mma16(float* c, const uint32_t* a, uint32_t b0, uint32_t b1) {
    asm volatile("mma.sync.aligned.m16n8k16.row.col.f32.bf16.bf16.f32 "
                 "{%0,%1,%2,%3}, {%4,%5,%6,%7}, {%8,%9}, {%0,%1,%2,%3};"
                 : "+f"(c[0]), "+f"(c[1]), "+f"(c[2]), "+f"(c[3])
                 : "r"(a[0]), "r"(a[1]), "r"(a[2]), "r"(a[3]), "r"(b0), "r"(b1));
}

__device__ __forceinline__ void ldmx4(uint32_t* r, uint32_t saddr) {
    asm volatile("ldmatrix.sync.aligned.m8n8.x4.shared.b16 {%0,%1,%2,%3}, [%4];"
                 : "=r"(r[0]), "=r"(r[1]), "=r"(r[2]), "=r"(r[3]) : "r"(saddr));
}
__device__ __forceinline__ void ldmx4t(uint32_t* r, uint32_t saddr) {
    asm volatile("ldmatrix.sync.aligned.m8n8.x4.trans.shared.b16 {%0,%1,%2,%3}, [%4];"
                 : "=r"(r[0]), "=r"(r[1]), "=r"(r[2]), "=r"(r[3]) : "r"(saddr));
}

__device__ __forceinline__ uint32_t s2u(const void* p) {
    return (uint32_t)__cvta_generic_to_shared(p);
}

// ===========================================================================
// bf16 3-term GEMM core: 128x128 tile, BK=32, 256 thr (8 warps 2m x 4n),
// warp = 64m x 32n. Double-buffered smem planes; ldmatrix fragments.
// A plane stride 40 bf16 (20 words): row banks 20r%32 all-distinct.
// B plane stride 136 bf16 (68 words): row banks 4r%32 all-distinct.
// ===========================================================================
#define GA_STRIDE 20
#define GB_STRIDE 68
#define GA_SIZE (128*GA_STRIDE)   // 2560 words
#define GB_SIZE (32*GB_STRIDE)    // 2176 words
#define OFF_AH(bf) ((bf)*GA_SIZE)
#define OFF_AL(bf) (2*GA_SIZE + (bf)*GA_SIZE)
#define OFF_BH(bf) (4*GA_SIZE + (bf)*GB_SIZE)
#define OFF_BL(bf) (4*GA_SIZE + 2*GB_SIZE + (bf)*GB_SIZE)
#define GEMM_SMEM_WORDS (4*GA_SIZE + 4*GB_SIZE)   // 18944 words = 75776 B

__device__ __forceinline__ void gemm_store_tile(uint32_t* sw, int bf,
                                                int arow, int acw, int brow, int bcw,
                                                const float4* pa, const float4* pb)
{
    uint32_t *AH = sw + OFF_AH(bf), *AL = sw + OFF_AL(bf);
    uint32_t *BH = sw + OFF_BH(bf), *BL = sw + OFF_BL(bf);
#pragma unroll
    for (int i = 0; i < 4; i++) {
        uint32_t h0, l0, h1, l1;
        split2(pa[i].x, pa[i].y, h0, l0); split2(pa[i].z, pa[i].w, h1, l1);
        int w = arow*GA_STRIDE + acw + 2*i;
        *(uint2*)(AH + w) = make_uint2(h0, h1);
        *(uint2*)(AL + w) = make_uint2(l0, l1);
        split2(pb[i].x, pb[i].y, h0, l0); split2(pb[i].z, pb[i].w, h1, l1);
        w = brow*GB_STRIDE + bcw + 2*i;
        *(uint2*)(BH + w) = make_uint2(h0, h1);
        *(uint2*)(BL + w) = make_uint2(l0, l1);
    }
}

__device__ __forceinline__ void gemm_bf16_core(
    const float* __restrict__ Ag, int lda,
    const float* __restrict__ Bg, int ldb,
    uint32_t* sw, float acc[4][4][4])
{
    const int tid = threadIdx.x, lane = tid & 31, wid = tid >> 5;
    const int wm = wid >> 2, wn = wid & 3;
    const int arow = tid >> 1, ace = (tid & 1)*16, acw = (tid & 1)*8;
    const int brow = tid >> 3, bce = (tid & 7)*16, bcw = (tid & 7)*8;
    const uint32_t sb = s2u(sw);

#pragma unroll
    for (int mt = 0; mt < 4; mt++)
#pragma unroll
        for (int j = 0; j < 4; j++)
#pragma unroll
            for (int u = 0; u < 4; u++) acc[mt][j][u] = 0.f;

    float4 pa[4], pb[4];
#pragma unroll
    for (int i = 0; i < 4; i++) {
        pa[i] = *(const float4*)(Ag + (size_t)arow*lda + ace + 4*i);
        pb[i] = *(const float4*)(Bg + (size_t)brow*ldb + bce + 4*i);
    }
    gemm_store_tile(sw, 0, arow, acw, brow, bcw, pa, pb);
    __syncthreads();

    const int larow = wm*64 + (lane & 15);
    const int lac   = ((lane >> 4) & 1)*4;
    const int lbrow = (lane & 7) + ((lane >> 3) & 1)*8;
    const int lbc   = wn*16 + ((lane >> 4) & 1)*4;

    for (int kt = 0; kt < 24; kt++) {
        const int cur = kt & 1;
        if (kt < 23) {
#pragma unroll
            for (int i = 0; i < 4; i++) {
                pa[i] = *(const float4*)(Ag + (size_t)arow*lda + (kt+1)*32 + ace + 4*i);
                pb[i] = *(const float4*)(Bg + (size_t)((kt+1)*32 + brow)*ldb + bce + 4*i);
            }
        }
        const uint32_t ahb = sb + OFF_AH(cur)*4, alb = sb + OFF_AL(cur)*4;
        const uint32_t bhb = sb + OFF_BH(cur)*4, blb = sb + OFF_BL(cur)*4;
#pragma unroll
        for (int kc = 0; kc < 2; kc++) {
            uint32_t ah[4][4], alr[4][4];
#pragma unroll
            for (int mt = 0; mt < 4; mt++) {
                uint32_t w = (uint32_t)((larow + mt*16)*GA_STRIDE + kc*8 + lac)*4;
                ldmx4(ah[mt],  ahb + w);
                ldmx4(alr[mt], alb + w);
            }
#pragma unroll
            for (int nn = 0; nn < 2; nn++) {
                uint32_t bh[4], bl[4];
                uint32_t w = (uint32_t)((kc*16 + lbrow)*GB_STRIDE + lbc + nn*8)*4;
                ldmx4t(bh, bhb + w);
                ldmx4t(bl, blb + w);
#pragma unroll
                for (int mt = 0; mt < 4; mt++) {
#pragma unroll
                    for (int s = 0; s < 2; s++) {
                        float* c = acc[mt][nn*2 + s];
                        mma16(c, ah[mt],  bh[2*s], bh[2*s+1]);
                        mma16(c, ah[mt],  bl[2*s], bl[2*s+1]);
                        mma16(c, alr[mt], bh[2*s], bh[2*s+1]);
                    }
                }
            }
        }
        if (kt < 23) gemm_store_tile(sw, (kt+1) & 1, arow, acw, brow, bcw, pa, pb);
        __syncthreads();
    }
}

// ---------------------------------------------------------------------------
// QKV projection: X[M,E] @ W[h][E][D] -> g_{Q,K,V} in [b][h][t][d]
// ---------------------------------------------------------------------------
__global__ __launch_bounds__(256)
void proj_bf16_kernel(const float* __restrict__ Xk, const float* __restrict__ Xv,
                      const float* __restrict__ Xq,
                      const float* __restrict__ Wk, const float* __restrict__ Wq,
                      const float* __restrict__ Wv)
{
    extern __shared__ uint32_t sw[];
    const float* X; const float* W; float* Out;
    if (blockIdx.z == 0)      { X = Xq; W = Wq; Out = g_Q; }
    else if (blockIdx.z == 1) { X = Xk; W = Wk; Out = g_K; }
    else                      { X = Xv; W = Wv; Out = g_V; }

    const int m0  = blockIdx.y * 128;
    const int h   = blockIdx.x >> 1;
    const int dB0 = (blockIdx.x & 1) * 128;

    float acc[4][4][4];
    gemm_bf16_core(X + (size_t)m0*NE, NE, W + (size_t)h*NE*ND + dB0, ND, sw, acc);

    const int lane = threadIdx.x & 31, wid = threadIdx.x >> 5;
    const int wm = wid >> 2, wn = wid & 3, g = lane >> 2, t = lane & 3;
#pragma unroll
    for (int mt = 0; mt < 4; mt++) {
        int r0 = m0 + wm*64 + mt*16 + g;
        int r1 = r0 + 8;
        int bb0 = r0 >> 11, tt0 = r0 & (NT-1);
        int bb1 = r1 >> 11, tt1 = r1 & (NT-1);
        float* o0 = Out + ((size_t)(bb0*NH + h)*NT + tt0)*ND + dB0;
        float* o1 = Out + ((size_t)(bb1*NH + h)*NT + tt1)*ND + dB0;
#pragma unroll
        for (int j = 0; j < 4; j++) {
            int c = wn*32 + j*8 + 2*t;
            *(float2*)(o0 + c) = make_float2(acc[mt][j][0], acc[mt][j][1]);
            *(float2*)(o1 + c) = make_float2(acc[mt][j][2], acc[mt][j][3]);
        }
    }
}

// ---------------------------------------------------------------------------
// Output projection: g_Z[M,E] @ Wo[E,E] + bo -> out[M,E]
// ---------------------------------------------------------------------------
__global__ __launch_bounds__(256)
void out_bf16_kernel(const float* __restrict__ Wo, const float* __restrict__ bo,
                     float* __restrict__ out)
{
    extern __shared__ uint32_t sw[];
    const int m0 = blockIdx.y * 128;
    const int c0 = blockIdx.x * 128;

    float acc[4][4][4];
    gemm_bf16_core(g_Z + (size_t)m0*NE, NE, Wo + c0, NE, sw, acc);

    const int lane = threadIdx.x & 31, wid = threadIdx.x >> 5;
    const int wm = wid >> 2, wn = wid & 3, g = lane >> 2, t = lane & 3;
#pragma unroll
    for (int mt = 0; mt < 4; mt++) {
        int r0 = m0 + wm*64 + mt*16 + g;
        int r1 = r0 + 8;
        float* o0 = out + (size_t)r0*NE + c0;
        float* o1 = out + (size_t)r1*NE + c0;
#pragma unroll
        for (int j = 0; j < 4; j++) {
            int c = wn*32 + j*8 + 2*t;
            float b0 = bo[c0 + c], b1 = bo[c0 + c + 1];
            *(float2*)(o0 + c) = make_float2(acc[mt][j][0] + b0, acc[mt][j][1] + b1);
            *(float2*)(o1 + c) = make_float2(acc[mt][j][2] + b0, acc[mt][j][3] + b1);
        }
    }
}

// ===========================================================================
// Flash attention, causal, bf16 3-term mma. BQ=BKV=64, D=256.
// Q/K/V planes [row][264 bf16] (132 words, banks 4r%32 distinct for ldmatrix).
// QK: 8 warps = 4 q-groups x 2 kv-halves; S staged fp32 in smem; softmax in
// fp32 (proven code); P re-split to bf16 planes (stride 72); PV: 8 warps =
// 4 q-groups x 2 d-halves, V fragments via ldmatrix.trans (row-major V).
// ===========================================================================
#define AW  132     // word stride of Q/K/V planes
#define PBW 36      // word stride of Pb planes
#define OFF_QH 0
#define OFF_QL (OFF_QH + 64*AW)
#define OFF_KH (OFF_QL + 64*AW)
#define OFF_KL (OFF_KH + 64*AW)
#define OFF_VH (OFF_KL + 64*AW)
#define OFF_VL (OFF_VH + 64*AW)
#define OFF_PS  (OFF_VL + 64*AW)          // fp32 S [64][68]  (aliased w/ Pb)
#define OFF_PBH OFF_PS
#define OFF_PBL (OFF_PBH + 64*PBW)
#define OFF_STAT (OFF_PS + 4608)
#define ATT_SMEM_WORDS (OFF_STAT + 192)   // 55488 words = 221952 B

__global__ __launch_bounds__(256)
void attn_kernel()
{
    extern __shared__ uint32_t sw[];
    const uint32_t sb = s2u(sw);
    float* Ps  = (float*)(sw + OFF_PS);
    float* m_s = (float*)(sw + OFF_STAT);
    float* l_s = m_s + 64;
    float* al_s = l_s + 64;

    const int tid = threadIdx.x, lane = tid & 31, wid = tid >> 5;
    const int bh = blockIdx.y, b = bh / NH, h = bh % NH;
    const int qt = (gridDim.x - 1) - blockIdx.x;   // heavy tiles first
    const int q0 = qt * 64;
    const size_t base = (size_t)(b*NH + h) * NT * ND;

    // Load Q -> bf16 hi/lo planes (once per CTA)
    {
        const float* Qg = g_Q + base + (size_t)q0 * ND;
#pragma unroll
        for (int it = 0; it < 16; it++) {
            int idx = tid + it*256, r = idx >> 6, f4 = idx & 63;
            float4 v = *(const float4*)(Qg + (size_t)r*ND + f4*4);
            uint32_t h0, l0, h1, l1;
            split2(v.x, v.y, h0, l0); split2(v.z, v.w, h1, l1);
            int w = r*AW + 2*f4;
            *(uint2*)(sw + OFF_QH + w) = make_uint2(h0, h1);
            *(uint2*)(sw + OFF_QL + w) = make_uint2(l0, l1);
        }
    }
    if (tid < 64) { m_s[tid] = -1e30f; l_s[tid] = 0.f; }

    float pacc[16][4];
#pragma unroll
    for (int i = 0; i < 16; i++)
#pragma unroll
        for (int u = 0; u < 4; u++) pacc[i][u] = 0.f;

    const int g = lane >> 2, t = lane & 3;
    const int wq = wid >> 1, wk = wid & 1;   // QK roles (q group / kv half)
    const int wd = wid & 1;                  // PV role (d half); q group = wq
    const int rS = tid >> 2, gS = tid & 3;   // softmax mapping

    // ldmatrix lane-address components
    const int qrow  = wq*16 + (lane & 15);
    const int qcw   = ((lane >> 4) & 1)*4;
    const int krow0 = wk*32 + (lane & 7) + ((lane >> 4) & 1)*8;  // non-trans B tiles
    const int kcw   = ((lane >> 3) & 1)*4;
    const int vrow0 = (lane & 7) + ((lane >> 3) & 1)*8;          // trans B tiles
    const int vcw   = wd*64 + ((lane >> 4) & 1)*4;

    for (int kt = 0; kt <= qt; kt++) {
        const int k0 = kt * 64;
        __syncthreads();   // prior PV done; Q planes ready on iter 0

        // Load K,V -> bf16 planes
        {
            const float* Kg = g_K + base + (size_t)k0 * ND;
            const float* Vg = g_V + base + (size_t)k0 * ND;
#pragma unroll
            for (int it = 0; it < 16; it++) {
                int idx = tid + it*256, r = idx >> 6, f4 = idx & 63;
                int w = r*AW + 2*f4;
                float4 v = *(const float4*)(Kg + (size_t)r*ND + f4*4);
                uint32_t h0, l0, h1, l1;
                split2(v.x, v.y, h0, l0); split2(v.z, v.w, h1, l1);
                *(uint2*)(sw + OFF_KH + w) = make_uint2(h0, h1);
                *(uint2*)(sw + OFF_KL + w) = make_uint2(l0, l1);
                v = *(const float4*)(Vg + (size_t)r*ND + f4*4);
                split2(v.x, v.y, h0, l0); split2(v.z, v.w, h1, l1);
                *(uint2*)(sw + OFF_VH + w) = make_uint2(h0, h1);
                *(uint2*)(sw + OFF_VL + w) = make_uint2(l0, l1);
            }
        }
        __syncthreads();

        // QK: S[64x64] raw scores -> Ps
        {
            float sfr[4][4];
#pragma unroll
            for (int j = 0; j < 4; j++)
#pragma unroll
                for (int u = 0; u < 4; u++) sfr[j][u] = 0.f;
#pragma unroll
            for (int c = 0; c < 16; c++) {          // d chunks of 16
                uint32_t qh[4], ql[4];
                uint32_t wqa = (uint32_t)(qrow*AW + c*8 + qcw)*4;
                ldmx4(qh, sb + OFF_QH*4 + wqa);
                ldmx4(ql, sb + OFF_QL*4 + wqa);
#pragma unroll
                for (int g2 = 0; g2 < 2; g2++) {    // kv n16 groups
                    uint32_t kh[4], kl[4];
                    uint32_t wka = (uint32_t)((krow0 + g2*16)*AW + c*8 + kcw)*4;
                    ldmx4(kh, sb + OFF_KH*4 + wka);
                    ldmx4(kl, sb + OFF_KL*4 + wka);
#pragma unroll
                    for (int s = 0; s < 2; s++) {
                        float* cc = sfr[g2*2 + s];
                        mma16(cc, qh, kh[2*s], kh[2*s+1]);
                        mma16(cc, qh, kl[2*s], kl[2*s+1]);
                        mma16(cc, ql, kh[2*s], kh[2*s+1]);
                    }
                }
            }
#pragma unroll
            for (int j = 0; j < 4; j++) {
                int col = wk*32 + j*8 + 2*t;
                int r0 = wq*16 + g;
                *(float2*)(Ps + r0*68 + col)     = make_float2(sfr[j][0], sfr[j][1]);
                *(float2*)(Ps + (r0+8)*68 + col) = make_float2(sfr[j][2], sfr[j][3]);
            }
        }
        __syncthreads();

        // Online softmax stage 1 (reads Ps, p's stay in regs)
        float pv[16];
        {
            float* Sr = Ps + rS*68 + gS*16;
            const bool diag = (kt == qt);
            float mloc = -1e30f;
#pragma unroll
            for (int c2 = 0; c2 < 16; c2++) {
                float x = Sr[c2] * ATT_SCALE;
                if (diag && (gS*16 + c2) > rS) x = -1e30f;
                pv[c2] = x;
                mloc = fmaxf(mloc, x);
            }
            mloc = fmaxf(mloc, __shfl_xor_sync(0xffffffffu, mloc, 1));
            mloc = fmaxf(mloc, __shfl_xor_sync(0xffffffffu, mloc, 2));
            float mold = m_s[rS];
            float mnew = fmaxf(mold, mloc);
            float suml = 0.f;
#pragma unroll
            for (int c2 = 0; c2 < 16; c2++) {
                float p = __expf(pv[c2] - mnew);
                pv[c2] = p;
                suml += p;
            }
            suml += __shfl_xor_sync(0xffffffffu, suml, 1);
            suml += __shfl_xor_sync(0xffffffffu, suml, 2);
            if (gS == 0) {
                float alpha = __expf(mold - mnew);
                l_s[rS]  = l_s[rS]*alpha + suml;
                m_s[rS]  = mnew;
                al_s[rS] = alpha;
            }
        }
        __syncthreads();   // all Ps reads done before Pb overwrites the region

        // Write P -> bf16 hi/lo planes
#pragma unroll
        for (int j = 0; j < 8; j++) {
            uint32_t hh, ll;
            split2(pv[2*j], pv[2*j+1], hh, ll);
            sw[OFF_PBH + rS*PBW + gS*8 + j] = hh;
            sw[OFF_PBL + rS*PBW + gS*8 + j] = ll;
        }
        __syncthreads();

        // PV: acc = acc*alpha + P @ V
        {
            float a0 = al_s[wq*16 + g], a1 = al_s[wq*16 + 8 + g];
#pragma unroll
            for (int i = 0; i < 16; i++) {
                pacc[i][0] *= a0; pacc[i][1] *= a0;
                pacc[i][2] *= a1; pacc[i][3] *= a1;
            }
            const int prow = wq*16 + (lane & 15);
            const int pcw  = ((lane >> 4) & 1)*4;
#pragma unroll
            for (int c = 0; c < 4; c++) {           // kv chunks of 16
                uint32_t ph[4], pl[4];
                uint32_t wpa = (uint32_t)(prow*PBW + c*8 + pcw)*4;
                ldmx4(ph, sb + OFF_PBH*4 + wpa);
                ldmx4(pl, sb + OFF_PBL*4 + wpa);
#pragma unroll
                for (int dn = 0; dn < 8; dn++) {    // d n16 groups in this half
                    uint32_t vh[4], vl[4];
                    uint32_t wva = (uint32_t)((c*16 + vrow0)*AW + vcw + dn*8)*4;
                    ldmx4t(vh, sb + OFF_VH*4 + wva);
                    ldmx4t(vl, sb + OFF_VL*4 + wva);
#pragma unroll
                    for (int s = 0; s < 2; s++) {
                        float* cc = pacc[dn*2 + s];
                        mma16(cc, ph, vh[2*s], vh[2*s+1]);
                        mma16(cc, ph, vl[2*s], vl[2*s+1]);
                        mma16(cc, pl, vh[2*s], vh[2*s+1]);
                    }
                }
            }
        }
    }

    // Epilogue: normalize, write g_Z[b][t][h*D + d]
    {
        float li0 = __fdividef(1.f, l_s[wq*16 + g]);
        float li1 = __fdividef(1.f, l_s[wq*16 + 8 + g]);
        float* Z0 = g_Z + ((size_t)b*NT + q0 + wq*16 + g)*NE + h*ND + wd*128;
        float* Z1 = Z0 + (size_t)8*NE;
#pragma unroll
        for (int i = 0; i < 16; i++) {
            int col = i*8 + 2*t;   // i = dn*2+s -> dn*16 + s*8
            *(float2*)(Z0 + col) = make_float2(pacc[i][0]*li0, pacc[i][1]*li0);
            *(float2*)(Z1 + col) = make_float2(pacc[i][2]*li1, pacc[i][3]*li1);
        }
    }
}

// ---------------------------------------------------------------------------
extern "C" void kernel_launch(void* const* d_in, const int* in_sizes, int n_in,
                              void* d_out, int out_size)
{
    const float* Xk = (const float*)d_in[0];
    const float* Xv = (const float*)d_in[1];
    const float* Xq = (const float*)d_in[2];
    const float* Wk = (const float*)d_in[3];
    const float* Wq = (const float*)d_in[4];
    const float* Wv = (const float*)d_in[5];
    const float* Wo = (const float*)d_in[6];
    const float* bo = (const float*)d_in[7];
    float* out = (float*)d_out;

    const int smemG = GEMM_SMEM_WORDS * 4;    // 75776 B
    const int smemA = ATT_SMEM_WORDS * 4;     // 221952 B
    cudaFuncSetAttribute(proj_bf16_kernel,
                         cudaFuncAttributeMaxDynamicSharedMemorySize, smemG);
    cudaFuncSetAttribute(out_bf16_kernel,
                         cudaFuncAttributeMaxDynamicSharedMemorySize, smemG);
    cudaFuncSetAttribute(attn_kernel,
                         cudaFuncAttributeMaxDynamicSharedMemorySize, smemA);

    dim3 gproj(6, NM/128, 3);   // (h*2 + d-half, m-tile, Q/K/V)
    proj_bf16_kernel<<<gproj, 256, smemG>>>(Xk, Xv, Xq, Wk, Wq, Wv);

    dim3 gattn(NT/64, NB*NH);
    attn_kernel<<<gattn, 256, smemA>>>();

    dim3 gout(NE/128, NM/128);
    out_bf16_kernel<<<gout, 256, smemG>>>(Wo, bo, out);
}